// round 6
// baseline (speedup 1.0000x reference)
#include <cuda_runtime.h>
#include <cuda_bf16.h>
#include <math.h>
#include <stdint.h>

// Problem constants
#define B_ 2
#define S_ 2048
#define H_ 4096
#define NH 32
#define HD 128
#define BS_ (B_ * S_)          // 4096 rows
#define QKV_N (3 * H_)         // 12288

// ---------------------------------------------------------------------------
// Scratch (static device globals)
// ---------------------------------------------------------------------------
__device__ float g_qkv[(size_t)BS_ * QKV_N];
__device__ __nv_bfloat16 g_xh[(size_t)BS_ * H_];
__device__ __nv_bfloat16 g_xl[(size_t)BS_ * H_];
__device__ __nv_bfloat16 g_wqh[(size_t)QKV_N * H_];
__device__ __nv_bfloat16 g_wql[(size_t)QKV_N * H_];
__device__ __nv_bfloat16 g_woh[(size_t)H_ * H_];
__device__ __nv_bfloat16 g_wol[(size_t)H_ * H_];
__device__ __nv_bfloat16 g_ch[(size_t)BS_ * H_];
__device__ __nv_bfloat16 g_cl[(size_t)BS_ * H_];
__device__ __nv_bfloat16 g_qh[(size_t)BS_ * H_];
__device__ __nv_bfloat16 g_ql[(size_t)BS_ * H_];
__device__ __nv_bfloat16 g_kh[(size_t)BS_ * H_];
__device__ __nv_bfloat16 g_kl[(size_t)BS_ * H_];
__device__ __nv_bfloat16 g_vth[(size_t)BS_ * H_];
__device__ __nv_bfloat16 g_vtl[(size_t)BS_ * H_];
__device__ float g_rcos[S_ * 64];
__device__ float g_rsin[S_ * 64];

// ---------------------------------------------------------------------------
// mma.sync + cp.async helpers
// ---------------------------------------------------------------------------
__device__ __forceinline__ uint32_t smem_u32(const void* p) {
    uint32_t a;
    asm("{ .reg .u64 t; cvta.to.shared.u64 t, %1; cvt.u32.u64 %0, t; }"
        : "=r"(a) : "l"(p));
    return a;
}

#define CP_ASYNC16(dst, src) \
    asm volatile("cp.async.cg.shared.global [%0], [%1], 16;" \
                 :: "r"(dst), "l"(src) : "memory")
#define CP_COMMIT() asm volatile("cp.async.commit_group;" ::: "memory")
#define CP_WAIT2()  asm volatile("cp.async.wait_group 2;" ::: "memory")
#define CP_WAIT1()  asm volatile("cp.async.wait_group 1;" ::: "memory")
#define CP_WAIT0()  asm volatile("cp.async.wait_group 0;" ::: "memory")

__device__ __forceinline__ void mma_bf16(float* d, const uint32_t* a,
                                         uint32_t b0, uint32_t b1) {
    asm volatile(
        "mma.sync.aligned.m16n8k16.row.col.f32.bf16.bf16.f32 "
        "{%0,%1,%2,%3}, {%4,%5,%6,%7}, {%8,%9}, {%0,%1,%2,%3};"
        : "+f"(d[0]), "+f"(d[1]), "+f"(d[2]), "+f"(d[3])
        : "r"(a[0]), "r"(a[1]), "r"(a[2]), "r"(a[3]), "r"(b0), "r"(b1));
}

__device__ __forceinline__ uint32_t packbf(float a, float b) {
    uint32_t lo = __bfloat16_as_ushort(__float2bfloat16(a));
    uint32_t hi = __bfloat16_as_ushort(__float2bfloat16(b));
    return lo | (hi << 16);
}

// ---------------------------------------------------------------------------
// bf16x3 mma.sync GEMM:  C[M,N] = A * B^T  (A [M,K], B [N,K])
// Tile 128x256, BK=32, 512 threads (16 warps; warp tile 32x64),
// 3-stage cp.async pipeline.  C = Ah*Bh + Al*Bh + Ah*Bl.
// ---------------------------------------------------------------------------
#define SA_STRIDE 80
#define OFF_AH 0
#define OFF_AL 10240
#define OFF_BH 20480
#define OFF_BL 40960
#define STAGE_BYTES 61440
#define GEMM_SMEM (3 * STAGE_BYTES)   // 184320

__global__ __launch_bounds__(512, 1) void gemm_bf16x3mma(
    const __nv_bfloat16* __restrict__ Ah, const __nv_bfloat16* __restrict__ Al,
    const __nv_bfloat16* __restrict__ Bh, const __nv_bfloat16* __restrict__ Bl,
    float* __restrict__ C, int Nglob, int K)
{
    extern __shared__ char smem[];
    const int tid  = threadIdx.x;
    const int lane = tid & 31;
    const int wid  = tid >> 5;          // 0..15
    const int wm = wid & 3;             // M sub-block of 32 rows
    const int wn = wid >> 2;            // N sub-block of 64 cols
    const int bm = blockIdx.x * 128;
    const int bn = blockIdx.y * 256;

    const uint32_t sb = smem_u32(smem);
    const int nchunk = K >> 5;

    auto load_chunk = [&](int c, int s) {
        const int k0 = c << 5;
        const uint32_t st = sb + s * STAGE_BYTES;
        // A: 128 rows x 4 segs (one per thread), hi+lo
        {
            const int r = tid >> 2, seg = tid & 3;
            const size_t go = (size_t)(bm + r) * K + k0 + seg * 8;
            const uint32_t so = r * SA_STRIDE + seg * 16;
            CP_ASYNC16(st + OFF_AH + so, Ah + go);
            CP_ASYNC16(st + OFF_AL + so, Al + go);
        }
        // B: 256 rows x 4 segs, hi+lo
        #pragma unroll
        for (int i = 0; i < 2; i++) {
            const int idx = tid + i * 512;
            const int r = idx >> 2, seg = idx & 3;
            const size_t go = (size_t)(bn + r) * K + k0 + seg * 8;
            const uint32_t so = r * SA_STRIDE + seg * 16;
            CP_ASYNC16(st + OFF_BH + so, Bh + go);
            CP_ASYNC16(st + OFF_BL + so, Bl + go);
        }
        CP_COMMIT();
    };

    float acc[2][8][4];
    #pragma unroll
    for (int mt = 0; mt < 2; mt++)
        #pragma unroll
        for (int nt = 0; nt < 8; nt++)
            #pragma unroll
            for (int j = 0; j < 4; j++) acc[mt][nt][j] = 0.f;

    load_chunk(0, 0);
    if (nchunk > 1) load_chunk(1, 1);

    const int arow = wm * 32 + (lane >> 2);
    const int brow = wn * 64 + (lane >> 2);
    const int acol = (lane & 3) * 4;

    for (int c = 0; c < nchunk; c++) {
        if (c + 2 < nchunk) { load_chunk(c + 2, (c + 2) % 3); CP_WAIT2(); }
        else if (c + 1 < nchunk) { CP_WAIT1(); }
        else { CP_WAIT0(); }
        __syncthreads();

        const char* st = smem + (c % 3) * STAGE_BYTES;
        const char* pAh = st + OFF_AH;
        const char* pAl = st + OFF_AL;
        const char* pBh = st + OFF_BH;
        const char* pBl = st + OFF_BL;

        #pragma unroll
        for (int ks = 0; ks < 2; ks++) {
            const int cb = ks * 32 + acol;
            uint32_t ah[2][4], al[2][4];
            #pragma unroll
            for (int mt = 0; mt < 2; mt++) {
                const int r0 = (arow + mt * 16) * SA_STRIDE;
                const int r8 = r0 + 8 * SA_STRIDE;
                ah[mt][0] = *(const uint32_t*)(pAh + r0 + cb);
                ah[mt][1] = *(const uint32_t*)(pAh + r8 + cb);
                ah[mt][2] = *(const uint32_t*)(pAh + r0 + cb + 16);
                ah[mt][3] = *(const uint32_t*)(pAh + r8 + cb + 16);
                al[mt][0] = *(const uint32_t*)(pAl + r0 + cb);
                al[mt][1] = *(const uint32_t*)(pAl + r8 + cb);
                al[mt][2] = *(const uint32_t*)(pAl + r0 + cb + 16);
                al[mt][3] = *(const uint32_t*)(pAl + r8 + cb + 16);
            }
            uint32_t bhf[8][2];
            #pragma unroll
            for (int nt = 0; nt < 8; nt++) {
                const int rb = (brow + nt * 8) * SA_STRIDE;
                bhf[nt][0] = *(const uint32_t*)(pBh + rb + cb);
                bhf[nt][1] = *(const uint32_t*)(pBh + rb + cb + 16);
            }
            #pragma unroll
            for (int nt = 0; nt < 8; nt++)
                #pragma unroll
                for (int mt = 0; mt < 2; mt++)
                    mma_bf16(acc[mt][nt], ah[mt], bhf[nt][0], bhf[nt][1]);
            #pragma unroll
            for (int nt = 0; nt < 8; nt++)
                #pragma unroll
                for (int mt = 0; mt < 2; mt++)
                    mma_bf16(acc[mt][nt], al[mt], bhf[nt][0], bhf[nt][1]);
            #pragma unroll
            for (int nt = 0; nt < 8; nt++) {
                const int rb = (brow + nt * 8) * SA_STRIDE;
                const uint32_t bl0 = *(const uint32_t*)(pBl + rb + cb);
                const uint32_t bl1 = *(const uint32_t*)(pBl + rb + cb + 16);
                #pragma unroll
                for (int mt = 0; mt < 2; mt++)
                    mma_bf16(acc[mt][nt], ah[mt], bl0, bl1);
            }
        }
        __syncthreads();
    }

    #pragma unroll
    for (int mt = 0; mt < 2; mt++) {
        const int row = bm + wm * 32 + mt * 16 + (lane >> 2);
        float* cp0 = C + (size_t)row * Nglob + bn + wn * 64 + (lane & 3) * 2;
        float* cp8 = cp0 + 8 * (size_t)Nglob;
        #pragma unroll
        for (int nt = 0; nt < 8; nt++) {
            *(float2*)(cp0 + nt * 8) = make_float2(acc[mt][nt][0], acc[mt][nt][1]);
            *(float2*)(cp8 + nt * 8) = make_float2(acc[mt][nt][2], acc[mt][nt][3]);
        }
    }
}

// ---------------------------------------------------------------------------
// Elementwise fp32 -> (bf16 hi, bf16 lo) split
// ---------------------------------------------------------------------------
__global__ void split_kernel(const float4* __restrict__ in,
                             uint2* __restrict__ h, uint2* __restrict__ l, int n4)
{
    const int i = blockIdx.x * blockDim.x + threadIdx.x;
    if (i >= n4) return;
    const float4 v = in[i];
    __nv_bfloat16 h0 = __float2bfloat16(v.x), h1 = __float2bfloat16(v.y);
    __nv_bfloat16 h2 = __float2bfloat16(v.z), h3 = __float2bfloat16(v.w);
    __nv_bfloat16 l0 = __float2bfloat16(v.x - __bfloat162float(h0));
    __nv_bfloat16 l1 = __float2bfloat16(v.y - __bfloat162float(h1));
    __nv_bfloat16 l2 = __float2bfloat16(v.z - __bfloat162float(h2));
    __nv_bfloat16 l3 = __float2bfloat16(v.w - __bfloat162float(h3));
    uint2 hh, ll;
    hh.x = (uint32_t)__bfloat16_as_ushort(h0) | ((uint32_t)__bfloat16_as_ushort(h1) << 16);
    hh.y = (uint32_t)__bfloat16_as_ushort(h2) | ((uint32_t)__bfloat16_as_ushort(h3) << 16);
    ll.x = (uint32_t)__bfloat16_as_ushort(l0) | ((uint32_t)__bfloat16_as_ushort(l1) << 16);
    ll.y = (uint32_t)__bfloat16_as_ushort(l2) | ((uint32_t)__bfloat16_as_ushort(l3) << 16);
    h[i] = hh; l[i] = ll;
}

// ---------------------------------------------------------------------------
// Transpose + split: W [K,N] fp32 -> Wt hi/lo [N,K] bf16
// ---------------------------------------------------------------------------
__global__ void transpose_split(const float* __restrict__ W,
                                __nv_bfloat16* __restrict__ Th,
                                __nv_bfloat16* __restrict__ Tl, int K, int N)
{
    __shared__ float t[32][33];
    const int tx = threadIdx.x, ty = threadIdx.y;
    const int nx = blockIdx.x * 32;
    const int ky = blockIdx.y * 32;
    #pragma unroll
    for (int j = 0; j < 32; j += 8)
        t[ty + j][tx] = W[(size_t)(ky + ty + j) * N + nx + tx];
    __syncthreads();
    #pragma unroll
    for (int j = 0; j < 32; j += 8) {
        const float v = t[tx][ty + j];
        const __nv_bfloat16 hi = __float2bfloat16(v);
        const __nv_bfloat16 lo = __float2bfloat16(v - __bfloat162float(hi));
        const size_t o = (size_t)(nx + ty + j) * K + ky + tx;
        Th[o] = hi; Tl[o] = lo;
    }
}

// ---------------------------------------------------------------------------
// RoPE cos/sin tables
// ---------------------------------------------------------------------------
__global__ void rope_tab(float* __restrict__ c, float* __restrict__ s)
{
    const int i = blockIdx.x * blockDim.x + threadIdx.x;
    const int t = i >> 6, p = i & 63;
    const float inv_freq = powf(10000.0f, -(float)p * (1.0f / 64.0f));
    float sn, cs;
    sincosf((float)t * inv_freq, &sn, &cs);
    c[i] = cs; s[i] = sn;
}

// ---------------------------------------------------------------------------
// prep_qkv: RoPE + scale + split hi/lo head-major; v transpose+split.
// ---------------------------------------------------------------------------
#define PREP_SMEM (128 * 133 * 4)

__global__ __launch_bounds__(256, 1) void prep_qkv(
    const float* __restrict__ qkv,
    const float* __restrict__ rc, const float* __restrict__ rs,
    __nv_bfloat16* __restrict__ Qh, __nv_bfloat16* __restrict__ Ql,
    __nv_bfloat16* __restrict__ Kh, __nv_bfloat16* __restrict__ Kl,
    __nv_bfloat16* __restrict__ Vh, __nv_bfloat16* __restrict__ Vl)
{
    extern __shared__ float ps[];
    const int tid = threadIdx.x;
    const int bh = blockIdx.y;
    const int b = bh >> 5, h = bh & 31;
    const int s0 = blockIdx.x * 128;
    const float scale = 0.08838834764831843f;

    #pragma unroll 4
    for (int i = 0; i < 32; i++) {
        const int idx = tid + i * 256;
        const int sr = idx >> 6, p = idx & 63;
        const int sg = s0 + sr;
        const size_t base = ((size_t)b * S_ + sg) * QKV_N + h * HD;
        const float cs = rc[sg * 64 + p], sn = rs[sg * 64 + p];
        const float q1 = qkv[base + p],        q2 = qkv[base + p + 64];
        const float k1 = qkv[base + H_ + p],   k2 = qkv[base + H_ + p + 64];
        const float qa = (q1 * cs - q2 * sn) * scale;
        const float qb = (q2 * cs + q1 * sn) * scale;
        const float ka = k1 * cs - k2 * sn;
        const float kb = k2 * cs + k1 * sn;
        const size_t ob = ((size_t)bh * S_ + sg) * HD;
        __nv_bfloat16 t;
        t = __float2bfloat16(qa); Qh[ob + p] = t;      Ql[ob + p]      = __float2bfloat16(qa - __bfloat162float(t));
        t = __float2bfloat16(qb); Qh[ob + p + 64] = t; Ql[ob + p + 64] = __float2bfloat16(qb - __bfloat162float(t));
        t = __float2bfloat16(ka); Kh[ob + p] = t;      Kl[ob + p]      = __float2bfloat16(ka - __bfloat162float(t));
        t = __float2bfloat16(kb); Kh[ob + p + 64] = t; Kl[ob + p + 64] = __float2bfloat16(kb - __bfloat162float(t));
    }

    #pragma unroll 4
    for (int i = 0; i < 64; i++) {
        const int idx = tid + i * 256;
        const int sr = idx >> 7, p = idx & 127;
        ps[sr * 133 + p] = qkv[((size_t)b * S_ + s0 + sr) * QKV_N + h * HD + 2 * H_ + p];
    }
    __syncthreads();
    #pragma unroll 4
    for (int i = 0; i < 64; i++) {
        const int idx = tid + i * 256;
        const int d = idx >> 7, sr = idx & 127;
        const float v = ps[sr * 133 + d];
        const __nv_bfloat16 hi = __float2bfloat16(v);
        const size_t o = ((size_t)bh * HD + d) * S_ + s0 + sr;
        Vh[o] = hi;
        Vl[o] = __float2bfloat16(v - __bfloat162float(hi));
    }
}

// ---------------------------------------------------------------------------
// Flash attention, mma.sync bf16x3 (unchanged from R4/R5)
// ---------------------------------------------------------------------------
#define FQ_LD 136
#define FV_LD 72
#define SQ_ELEMS (128 * FQ_LD)
#define SK_ELEMS (64 * FQ_LD)
#define SV_ELEMS (128 * FV_LD)
#define FSTAGE (2 * SK_ELEMS + 2 * SV_ELEMS)
#define FLASH_SMEM ((2 * SQ_ELEMS + 2 * FSTAGE) * 2)

__global__ __launch_bounds__(256, 1) void flash_mma(
    const __nv_bfloat16* __restrict__ Qh, const __nv_bfloat16* __restrict__ Ql,
    const __nv_bfloat16* __restrict__ Kh, const __nv_bfloat16* __restrict__ Kl,
    const __nv_bfloat16* __restrict__ Vh, const __nv_bfloat16* __restrict__ Vl,
    __nv_bfloat16* __restrict__ Ch, __nv_bfloat16* __restrict__ Cl)
{
    extern __shared__ __nv_bfloat16 fs[];
    const int tid = threadIdx.x;
    const int lane = tid & 31;
    const int w = tid >> 5;
    const int qblk = blockIdx.x;
    const int bh = blockIdx.y;
    const int b = bh >> 5, h = bh & 31;
    const int q0 = qblk * 128;
    const uint32_t sb = smem_u32(fs);

    const size_t hoff = (size_t)bh * S_ * HD;
    const size_t voff = (size_t)bh * HD * S_;

    #pragma unroll
    for (int i = 0; i < 8; i++) {
        const int idx = tid + i * 256;
        const int r = idx >> 4, seg = idx & 15;
        const size_t go = hoff + (size_t)(q0 + r) * HD + seg * 8;
        const uint32_t so = (r * FQ_LD + seg * 8) * 2;
        CP_ASYNC16(sb + so, Qh + go);
        CP_ASYNC16(sb + SQ_ELEMS * 2 + so, Ql + go);
    }

    auto load_kv = [&](int t, int s) {
        const int k0 = t * 64;
        const uint32_t st = sb + (2 * SQ_ELEMS + s * FSTAGE) * 2;
        #pragma unroll
        for (int i = 0; i < 4; i++) {
            const int idx = tid + i * 256;
            const int r = idx >> 4, seg = idx & 15;
            const size_t go = hoff + (size_t)(k0 + r) * HD + seg * 8;
            const uint32_t so = (r * FQ_LD + seg * 8) * 2;
            CP_ASYNC16(st + so, Kh + go);
            CP_ASYNC16(st + SK_ELEMS * 2 + so, Kl + go);
        }
        #pragma unroll
        for (int i = 0; i < 4; i++) {
            const int idx = tid + i * 256;
            const int r = idx >> 3, seg = idx & 7;
            const size_t go = voff + (size_t)r * S_ + k0 + seg * 8;
            const uint32_t so = (2 * SK_ELEMS + r * FV_LD + seg * 8) * 2;
            CP_ASYNC16(st + so, Vh + go);
            CP_ASYNC16(st + SV_ELEMS * 2 + so, Vl + go);
        }
        CP_COMMIT();
    };

    load_kv(0, 0);

    float O[16][4];
    #pragma unroll
    for (int i = 0; i < 16; i++)
        #pragma unroll
        for (int j = 0; j < 4; j++) O[i][j] = 0.f;
    float m0 = -1e30f, m1 = -1e30f, l0 = 0.f, l1 = 0.f;

    const int r0 = w * 16 + (lane >> 2);
    const int cq = (lane & 3) * 2;
    const int ntiles = 2 * qblk + 2;

    for (int t = 0; t < ntiles; t++) {
        if (t + 1 < ntiles) { load_kv(t + 1, (t + 1) & 1); CP_WAIT1(); }
        else                { CP_WAIT0(); }
        __syncthreads();

        const __nv_bfloat16* sQh = fs;
        const __nv_bfloat16* sQl = fs + SQ_ELEMS;
        const __nv_bfloat16* sKh = fs + 2 * SQ_ELEMS + (t & 1) * FSTAGE;
        const __nv_bfloat16* sKl = sKh + SK_ELEMS;
        const __nv_bfloat16* sVh = sKl + SK_ELEMS;
        const __nv_bfloat16* sVl = sVh + SV_ELEMS;

        float Sf[8][4];
        #pragma unroll
        for (int nt = 0; nt < 8; nt++)
            #pragma unroll
            for (int j = 0; j < 4; j++) Sf[nt][j] = 0.f;

        #pragma unroll
        for (int kk = 0; kk < 8; kk++) {
            uint32_t ah[4], al[4];
            const __nv_bfloat16* qp = sQh + r0 * FQ_LD + kk * 16 + cq;
            const __nv_bfloat16* qp2 = sQl + r0 * FQ_LD + kk * 16 + cq;
            ah[0] = *(const uint32_t*)(qp);
            ah[1] = *(const uint32_t*)(qp + 8 * FQ_LD);
            ah[2] = *(const uint32_t*)(qp + 8);
            ah[3] = *(const uint32_t*)(qp + 8 * FQ_LD + 8);
            al[0] = *(const uint32_t*)(qp2);
            al[1] = *(const uint32_t*)(qp2 + 8 * FQ_LD);
            al[2] = *(const uint32_t*)(qp2 + 8);
            al[3] = *(const uint32_t*)(qp2 + 8 * FQ_LD + 8);
            uint32_t khf[8][2];
            #pragma unroll
            for (int nt = 0; nt < 8; nt++) {
                const int n = nt * 8 + (lane >> 2);
                const __nv_bfloat16* kp = sKh + n * FQ_LD + kk * 16 + cq;
                khf[nt][0] = *(const uint32_t*)(kp);
                khf[nt][1] = *(const uint32_t*)(kp + 8);
            }
            #pragma unroll
            for (int nt = 0; nt < 8; nt++)
                mma_bf16(Sf[nt], ah, khf[nt][0], khf[nt][1]);
            #pragma unroll
            for (int nt = 0; nt < 8; nt++)
                mma_bf16(Sf[nt], al, khf[nt][0], khf[nt][1]);
            #pragma unroll
            for (int nt = 0; nt < 8; nt++) {
                const int n = nt * 8 + (lane >> 2);
                const __nv_bfloat16* kp2 = sKl + n * FQ_LD + kk * 16 + cq;
                mma_bf16(Sf[nt], ah, *(const uint32_t*)(kp2),
                                     *(const uint32_t*)(kp2 + 8));
            }
        }

        const int k0 = t * 64;
        const int qg0 = q0 + r0, qg1 = qg0 + 8;
        if (k0 + 63 > q0 + w * 16) {
            #pragma unroll
            for (int nt = 0; nt < 8; nt++) {
                const int kv = k0 + nt * 8 + cq;
                if (kv     > qg0) Sf[nt][0] = -1e30f;
                if (kv + 1 > qg0) Sf[nt][1] = -1e30f;
                if (kv     > qg1) Sf[nt][2] = -1e30f;
                if (kv + 1 > qg1) Sf[nt][3] = -1e30f;
            }
        }
        float mx0 = -1e30f, mx1 = -1e30f;
        #pragma unroll
        for (int nt = 0; nt < 8; nt++) {
            mx0 = fmaxf(mx0, fmaxf(Sf[nt][0], Sf[nt][1]));
            mx1 = fmaxf(mx1, fmaxf(Sf[nt][2], Sf[nt][3]));
        }
        mx0 = fmaxf(mx0, __shfl_xor_sync(0xffffffffu, mx0, 1));
        mx0 = fmaxf(mx0, __shfl_xor_sync(0xffffffffu, mx0, 2));
        mx1 = fmaxf(mx1, __shfl_xor_sync(0xffffffffu, mx1, 1));
        mx1 = fmaxf(mx1, __shfl_xor_sync(0xffffffffu, mx1, 2));

        const float mn0 = fmaxf(m0, mx0), mn1 = fmaxf(m1, mx1);
        const float a0 = __expf(m0 - mn0), a1 = __expf(m1 - mn1);
        m0 = mn0; m1 = mn1;

        float s0 = 0.f, s1 = 0.f;
        uint32_t Ph[8][2], Pl[8][2];
        #pragma unroll
        for (int nt = 0; nt < 8; nt++) {
            const float p00 = __expf(Sf[nt][0] - mn0);
            const float p01 = __expf(Sf[nt][1] - mn0);
            const float p10 = __expf(Sf[nt][2] - mn1);
            const float p11 = __expf(Sf[nt][3] - mn1);
            s0 += p00 + p01; s1 += p10 + p11;
            const __nv_bfloat16 h00 = __float2bfloat16(p00);
            const __nv_bfloat16 h01 = __float2bfloat16(p01);
            const __nv_bfloat16 h10 = __float2bfloat16(p10);
            const __nv_bfloat16 h11 = __float2bfloat16(p11);
            Ph[nt][0] = (uint32_t)__bfloat16_as_ushort(h00) | ((uint32_t)__bfloat16_as_ushort(h01) << 16);
            Ph[nt][1] = (uint32_t)__bfloat16_as_ushort(h10) | ((uint32_t)__bfloat16_as_ushort(h11) << 16);
            Pl[nt][0] = packbf(p00 - __bfloat162float(h00), p01 - __bfloat162float(h01));
            Pl[nt][1] = packbf(p10 - __bfloat162float(h10), p11 - __bfloat162float(h11));
        }
        s0 += __shfl_xor_sync(0xffffffffu, s0, 1);
        s0 += __shfl_xor_sync(0xffffffffu, s0, 2);
        s1 += __shfl_xor_sync(0xffffffffu, s1, 1);
        s1 += __shfl_xor_sync(0xffffffffu, s1, 2);
        l0 = l0 * a0 + s0;
        l1 = l1 * a1 + s1;

        #pragma unroll
        for (int i = 0; i < 16; i++) {
            O[i][0] *= a0; O[i][1] *= a0; O[i][2] *= a1; O[i][3] *= a1;
        }

        #pragma unroll
        for (int ks = 0; ks < 4; ks++) {
            const uint32_t ah[4] = {Ph[2 * ks][0], Ph[2 * ks][1],
                                    Ph[2 * ks + 1][0], Ph[2 * ks + 1][1]};
            const uint32_t al[4] = {Pl[2 * ks][0], Pl[2 * ks][1],
                                    Pl[2 * ks + 1][0], Pl[2 * ks + 1][1]};
            #pragma unroll
            for (int nt2 = 0; nt2 < 16; nt2++) {
                const int nd = nt2 * 8 + (lane >> 2);
                const __nv_bfloat16* vp = sVh + nd * FV_LD + ks * 16 + cq;
                mma_bf16(O[nt2], ah, *(const uint32_t*)(vp),
                                     *(const uint32_t*)(vp + 8));
            }
            #pragma unroll
            for (int nt2 = 0; nt2 < 16; nt2++) {
                const int nd = nt2 * 8 + (lane >> 2);
                const __nv_bfloat16* vp2 = sVl + nd * FV_LD + ks * 16 + cq;
                mma_bf16(O[nt2], ah, *(const uint32_t*)(vp2),
                                     *(const uint32_t*)(vp2 + 8));
            }
            #pragma unroll
            for (int nt2 = 0; nt2 < 16; nt2++) {
                const int nd = nt2 * 8 + (lane >> 2);
                const __nv_bfloat16* vp = sVh + nd * FV_LD + ks * 16 + cq;
                mma_bf16(O[nt2], al, *(const uint32_t*)(vp),
                                     *(const uint32_t*)(vp + 8));
            }
        }
        __syncthreads();
    }

    const float inv0 = 1.f / l0, inv1 = 1.f / l1;
    const int row0 = q0 + w * 16 + (lane >> 2);
    const size_t o0 = ((size_t)b * S_ + row0) * H_ + h * HD + cq;
    const size_t o1 = o0 + 8 * (size_t)H_;
    #pragma unroll
    for (int nt2 = 0; nt2 < 16; nt2++) {
        const float f0 = O[nt2][0] * inv0, f1 = O[nt2][1] * inv0;
        const float f2 = O[nt2][2] * inv1, f3 = O[nt2][3] * inv1;
        const __nv_bfloat16 h0 = __float2bfloat16(f0), h1 = __float2bfloat16(f1);
        const __nv_bfloat16 h2 = __float2bfloat16(f2), h3 = __float2bfloat16(f3);
        *(uint32_t*)&Ch[o0 + nt2 * 8] =
            (uint32_t)__bfloat16_as_ushort(h0) | ((uint32_t)__bfloat16_as_ushort(h1) << 16);
        *(uint32_t*)&Ch[o1 + nt2 * 8] =
            (uint32_t)__bfloat16_as_ushort(h2) | ((uint32_t)__bfloat16_as_ushort(h3) << 16);
        *(uint32_t*)&Cl[o0 + nt2 * 8] =
            packbf(f0 - __bfloat162float(h0), f1 - __bfloat162float(h1));
        *(uint32_t*)&Cl[o1 + nt2 * 8] =
            packbf(f2 - __bfloat162float(h2), f3 - __bfloat162float(h3));
    }
}

// ---------------------------------------------------------------------------
// Launch
// ---------------------------------------------------------------------------
extern "C" void kernel_launch(void* const* d_in, const int* in_sizes, int n_in,
                              void* d_out, int out_size)
{
    const float* x    = (const float*)d_in[0];
    const float* Wqkv = (const float*)d_in[1];
    const float* Wo   = (const float*)d_in[2];
    float* out = (float*)d_out;

    float *qkv, *rc, *rs;
    __nv_bfloat16 *xh, *xl, *wqh, *wql, *woh, *wol, *ch, *cl;
    __nv_bfloat16 *qh, *ql, *kh, *kl, *vth, *vtl;
    cudaGetSymbolAddress((void**)&qkv, g_qkv);
    cudaGetSymbolAddress((void**)&rc, g_rcos);
    cudaGetSymbolAddress((void**)&rs, g_rsin);
    cudaGetSymbolAddress((void**)&xh, g_xh);
    cudaGetSymbolAddress((void**)&xl, g_xl);
    cudaGetSymbolAddress((void**)&wqh, g_wqh);
    cudaGetSymbolAddress((void**)&wql, g_wql);
    cudaGetSymbolAddress((void**)&woh, g_woh);
    cudaGetSymbolAddress((void**)&wol, g_wol);
    cudaGetSymbolAddress((void**)&ch, g_ch);
    cudaGetSymbolAddress((void**)&cl, g_cl);
    cudaGetSymbolAddress((void**)&qh, g_qh);
    cudaGetSymbolAddress((void**)&ql, g_ql);
    cudaGetSymbolAddress((void**)&kh, g_kh);
    cudaGetSymbolAddress((void**)&kl, g_kl);
    cudaGetSymbolAddress((void**)&vth, g_vth);
    cudaGetSymbolAddress((void**)&vtl, g_vtl);

    cudaFuncSetAttribute(gemm_bf16x3mma,
                         cudaFuncAttributeMaxDynamicSharedMemorySize, GEMM_SMEM);
    cudaFuncSetAttribute(prep_qkv,
                         cudaFuncAttributeMaxDynamicSharedMemorySize, PREP_SMEM);
    cudaFuncSetAttribute(flash_mma,
                         cudaFuncAttributeMaxDynamicSharedMemorySize, FLASH_SMEM);

    {
        const int n4 = (BS_ * H_) / 4;
        split_kernel<<<n4 / 256, 256>>>((const float4*)x, (uint2*)xh, (uint2*)xl, n4);
    }
    {
        dim3 grid(QKV_N / 32, H_ / 32), blk(32, 8);
        transpose_split<<<grid, blk>>>(Wqkv, wqh, wql, H_, QKV_N);
    }
    {
        dim3 grid(H_ / 32, H_ / 32), blk(32, 8);
        transpose_split<<<grid, blk>>>(Wo, woh, wol, H_, H_);
    }
    rope_tab<<<(S_ * 64) / 256, 256>>>(rc, rs);

    {
        dim3 grid(BS_ / 128, QKV_N / 256);
        gemm_bf16x3mma<<<grid, 512, GEMM_SMEM>>>(xh, xl, wqh, wql, qkv, QKV_N, H_);
    }
    {
        dim3 grid(S_ / 128, B_ * NH);
        prep_qkv<<<grid, 256, PREP_SMEM>>>(qkv, rc, rs, qh, ql, kh, kl, vth, vtl);
    }
    {
        dim3 grid(S_ / 128, B_ * NH);
        flash_mma<<<grid, 256, FLASH_SMEM>>>(qh, ql, kh, kl, vth, vtl, ch, cl);
    }
    {
        dim3 grid(BS_ / 128, H_ / 256);
        gemm_bf16x3mma<<<grid, 512, GEMM_SMEM>>>(ch, cl, woh, wol, out, H_, H_);
    }
}

// round 7
// speedup vs baseline: 1.1473x; 1.1473x over previous
#include <cuda_runtime.h>
#include <cuda_bf16.h>
#include <math.h>
#include <stdint.h>

// Problem constants
#define B_ 2
#define S_ 2048
#define H_ 4096
#define NH 32
#define HD 128
#define BS_ (B_ * S_)          // 4096 rows
#define QKV_N (3 * H_)         // 12288

// ---------------------------------------------------------------------------
// Scratch (static device globals)
// ---------------------------------------------------------------------------
__device__ float g_qkv[(size_t)BS_ * QKV_N];
__device__ __nv_bfloat16 g_xh[(size_t)BS_ * H_];
__device__ __nv_bfloat16 g_xl[(size_t)BS_ * H_];
__device__ __nv_bfloat16 g_wqh[(size_t)QKV_N * H_];
__device__ __nv_bfloat16 g_wql[(size_t)QKV_N * H_];
__device__ __nv_bfloat16 g_woh[(size_t)H_ * H_];
__device__ __nv_bfloat16 g_wol[(size_t)H_ * H_];
__device__ __nv_bfloat16 g_ch[(size_t)BS_ * H_];
__device__ __nv_bfloat16 g_cl[(size_t)BS_ * H_];
__device__ __nv_bfloat16 g_qh[(size_t)BS_ * H_];
__device__ __nv_bfloat16 g_ql[(size_t)BS_ * H_];
__device__ __nv_bfloat16 g_kh[(size_t)BS_ * H_];
__device__ __nv_bfloat16 g_kl[(size_t)BS_ * H_];
__device__ __nv_bfloat16 g_vth[(size_t)BS_ * H_];
__device__ __nv_bfloat16 g_vtl[(size_t)BS_ * H_];
__device__ float g_rcos[S_ * 64];
__device__ float g_rsin[S_ * 64];

// ---------------------------------------------------------------------------
// mma.sync + cp.async helpers
// ---------------------------------------------------------------------------
__device__ __forceinline__ uint32_t smem_u32(const void* p) {
    uint32_t a;
    asm("{ .reg .u64 t; cvta.to.shared.u64 t, %1; cvt.u32.u64 %0, t; }"
        : "=r"(a) : "l"(p));
    return a;
}

#define CP_ASYNC16(dst, src) \
    asm volatile("cp.async.cg.shared.global [%0], [%1], 16;" \
                 :: "r"(dst), "l"(src) : "memory")
#define CP_COMMIT() asm volatile("cp.async.commit_group;" ::: "memory")
#define CP_WAIT1()  asm volatile("cp.async.wait_group 1;" ::: "memory")
#define CP_WAIT0()  asm volatile("cp.async.wait_group 0;" ::: "memory")

__device__ __forceinline__ void mma_bf16(float* d, const uint32_t* a,
                                         uint32_t b0, uint32_t b1) {
    asm volatile(
        "mma.sync.aligned.m16n8k16.row.col.f32.bf16.bf16.f32 "
        "{%0,%1,%2,%3}, {%4,%5,%6,%7}, {%8,%9}, {%0,%1,%2,%3};"
        : "+f"(d[0]), "+f"(d[1]), "+f"(d[2]), "+f"(d[3])
        : "r"(a[0]), "r"(a[1]), "r"(a[2]), "r"(a[3]), "r"(b0), "r"(b1));
}

__device__ __forceinline__ uint32_t packbf(float a, float b) {
    uint32_t lo = __bfloat16_as_ushort(__float2bfloat16(a));
    uint32_t hi = __bfloat16_as_ushort(__float2bfloat16(b));
    return lo | (hi << 16);
}

// ---------------------------------------------------------------------------
// bf16x3 mma.sync GEMM:  C[M,N] = A * B^T  (A [M,K], B [N,K])
// Tile 128x256, BK=64, 256 threads (8 warps; warp tile 64x64),
// 2-stage cp.async pipeline.  C = Ah*Bh + Al*Bh + Ah*Bl.
// smem row stride 144B (64 bf16 = 128B + 16B pad) -> conflict-free frags.
// ---------------------------------------------------------------------------
#define SA_STRIDE 144
#define OFF_AH 0
#define OFF_AL (128 * SA_STRIDE)                // 18432
#define OFF_BH (2 * 128 * SA_STRIDE)            // 36864
#define OFF_BL (2 * 128 * SA_STRIDE + 256 * SA_STRIDE)  // 73728
#define STAGE_BYTES (2 * 128 * SA_STRIDE + 2 * 256 * SA_STRIDE)  // 110592
#define GEMM_SMEM (2 * STAGE_BYTES)             // 221184

__global__ __launch_bounds__(256, 1) void gemm_bf16x3mma(
    const __nv_bfloat16* __restrict__ Ah, const __nv_bfloat16* __restrict__ Al,
    const __nv_bfloat16* __restrict__ Bh, const __nv_bfloat16* __restrict__ Bl,
    float* __restrict__ C, int Nglob, int K)
{
    extern __shared__ char smem[];
    const int tid  = threadIdx.x;
    const int lane = tid & 31;
    const int wid  = tid >> 5;
    const int wm = wid & 1;
    const int wn = wid >> 1;
    const int bm = blockIdx.x * 128;
    const int bn = blockIdx.y * 256;

    const uint32_t sb = smem_u32(smem);
    const int nchunk = K >> 6;        // BK=64

    auto load_chunk = [&](int c, int s) {
        const int k0 = c << 6;
        const uint32_t st = sb + s * STAGE_BYTES;
        // A: 128 rows x 8 segs of 16B, hi+lo
        #pragma unroll
        for (int i = 0; i < 4; i++) {
            const int idx = tid + i * 256;          // 0..1023
            const int r = idx >> 3, seg = idx & 7;
            const size_t go = (size_t)(bm + r) * K + k0 + seg * 8;
            const uint32_t so = r * SA_STRIDE + seg * 16;
            CP_ASYNC16(st + OFF_AH + so, Ah + go);
            CP_ASYNC16(st + OFF_AL + so, Al + go);
        }
        // B: 256 rows x 8 segs, hi+lo
        #pragma unroll
        for (int i = 0; i < 8; i++) {
            const int idx = tid + i * 256;          // 0..2047
            const int r = idx >> 3, seg = idx & 7;
            const size_t go = (size_t)(bn + r) * K + k0 + seg * 8;
            const uint32_t so = r * SA_STRIDE + seg * 16;
            CP_ASYNC16(st + OFF_BH + so, Bh + go);
            CP_ASYNC16(st + OFF_BL + so, Bl + go);
        }
        CP_COMMIT();
    };

    float acc[4][8][4];
    #pragma unroll
    for (int mt = 0; mt < 4; mt++)
        #pragma unroll
        for (int nt = 0; nt < 8; nt++)
            #pragma unroll
            for (int j = 0; j < 4; j++) acc[mt][nt][j] = 0.f;

    load_chunk(0, 0);
    if (nchunk > 1) load_chunk(1, 1);

    const int arow = wm * 64 + (lane >> 2);
    const int brow = wn * 64 + (lane >> 2);
    const int acol = (lane & 3) * 4;

    for (int c = 0; c < nchunk; c++) {
        if (c + 1 < nchunk) { CP_WAIT1(); } else { CP_WAIT0(); }
        __syncthreads();

        const char* st = smem + (c & 1) * STAGE_BYTES;
        const char* pAh = st + OFF_AH;
        const char* pAl = st + OFF_AL;
        const char* pBh = st + OFF_BH;
        const char* pBl = st + OFF_BL;

        #pragma unroll
        for (int ks = 0; ks < 4; ks++) {
            const int cb = ks * 32 + acol;
            uint32_t ah[4][4], al[4][4];
            #pragma unroll
            for (int mt = 0; mt < 4; mt++) {
                const int r0 = (arow + mt * 16) * SA_STRIDE;
                const int r8 = r0 + 8 * SA_STRIDE;
                ah[mt][0] = *(const uint32_t*)(pAh + r0 + cb);
                ah[mt][1] = *(const uint32_t*)(pAh + r8 + cb);
                ah[mt][2] = *(const uint32_t*)(pAh + r0 + cb + 16);
                ah[mt][3] = *(const uint32_t*)(pAh + r8 + cb + 16);
                al[mt][0] = *(const uint32_t*)(pAl + r0 + cb);
                al[mt][1] = *(const uint32_t*)(pAl + r8 + cb);
                al[mt][2] = *(const uint32_t*)(pAl + r0 + cb + 16);
                al[mt][3] = *(const uint32_t*)(pAl + r8 + cb + 16);
            }
            uint32_t bhf[8][2];
            #pragma unroll
            for (int nt = 0; nt < 8; nt++) {
                const int rb = (brow + nt * 8) * SA_STRIDE;
                bhf[nt][0] = *(const uint32_t*)(pBh + rb + cb);
                bhf[nt][1] = *(const uint32_t*)(pBh + rb + cb + 16);
            }
            #pragma unroll
            for (int nt = 0; nt < 8; nt++)
                #pragma unroll
                for (int mt = 0; mt < 4; mt++)
                    mma_bf16(acc[mt][nt], ah[mt], bhf[nt][0], bhf[nt][1]);
            #pragma unroll
            for (int nt = 0; nt < 8; nt++)
                #pragma unroll
                for (int mt = 0; mt < 4; mt++)
                    mma_bf16(acc[mt][nt], al[mt], bhf[nt][0], bhf[nt][1]);
            #pragma unroll
            for (int nt = 0; nt < 8; nt++) {
                const int rb = (brow + nt * 8) * SA_STRIDE;
                const uint32_t bl0 = *(const uint32_t*)(pBl + rb + cb);
                const uint32_t bl1 = *(const uint32_t*)(pBl + rb + cb + 16);
                #pragma unroll
                for (int mt = 0; mt < 4; mt++)
                    mma_bf16(acc[mt][nt], ah[mt], bl0, bl1);
            }
        }
        __syncthreads();
        if (c + 2 < nchunk) load_chunk(c + 2, c & 1);
    }

    #pragma unroll
    for (int mt = 0; mt < 4; mt++) {
        const int row = bm + wm * 64 + mt * 16 + (lane >> 2);
        float* cp0 = C + (size_t)row * Nglob + bn + wn * 64 + (lane & 3) * 2;
        float* cp8 = cp0 + 8 * (size_t)Nglob;
        #pragma unroll
        for (int nt = 0; nt < 8; nt++) {
            *(float2*)(cp0 + nt * 8) = make_float2(acc[mt][nt][0], acc[mt][nt][1]);
            *(float2*)(cp8 + nt * 8) = make_float2(acc[mt][nt][2], acc[mt][nt][3]);
        }
    }
}

// ---------------------------------------------------------------------------
// Elementwise fp32 -> (bf16 hi, bf16 lo) split
// ---------------------------------------------------------------------------
__global__ void split_kernel(const float4* __restrict__ in,
                             uint2* __restrict__ h, uint2* __restrict__ l, int n4)
{
    const int i = blockIdx.x * blockDim.x + threadIdx.x;
    if (i >= n4) return;
    const float4 v = in[i];
    __nv_bfloat16 h0 = __float2bfloat16(v.x), h1 = __float2bfloat16(v.y);
    __nv_bfloat16 h2 = __float2bfloat16(v.z), h3 = __float2bfloat16(v.w);
    __nv_bfloat16 l0 = __float2bfloat16(v.x - __bfloat162float(h0));
    __nv_bfloat16 l1 = __float2bfloat16(v.y - __bfloat162float(h1));
    __nv_bfloat16 l2 = __float2bfloat16(v.z - __bfloat162float(h2));
    __nv_bfloat16 l3 = __float2bfloat16(v.w - __bfloat162float(h3));
    uint2 hh, ll;
    hh.x = (uint32_t)__bfloat16_as_ushort(h0) | ((uint32_t)__bfloat16_as_ushort(h1) << 16);
    hh.y = (uint32_t)__bfloat16_as_ushort(h2) | ((uint32_t)__bfloat16_as_ushort(h3) << 16);
    ll.x = (uint32_t)__bfloat16_as_ushort(l0) | ((uint32_t)__bfloat16_as_ushort(l1) << 16);
    ll.y = (uint32_t)__bfloat16_as_ushort(l2) | ((uint32_t)__bfloat16_as_ushort(l3) << 16);
    h[i] = hh; l[i] = ll;
}

// ---------------------------------------------------------------------------
// Transpose + split: W [K,N] fp32 -> Wt hi/lo [N,K] bf16
// ---------------------------------------------------------------------------
__global__ void transpose_split(const float* __restrict__ W,
                                __nv_bfloat16* __restrict__ Th,
                                __nv_bfloat16* __restrict__ Tl, int K, int N)
{
    __shared__ float t[32][33];
    const int tx = threadIdx.x, ty = threadIdx.y;
    const int nx = blockIdx.x * 32;
    const int ky = blockIdx.y * 32;
    #pragma unroll
    for (int j = 0; j < 32; j += 8)
        t[ty + j][tx] = W[(size_t)(ky + ty + j) * N + nx + tx];
    __syncthreads();
    #pragma unroll
    for (int j = 0; j < 32; j += 8) {
        const float v = t[tx][ty + j];
        const __nv_bfloat16 hi = __float2bfloat16(v);
        const __nv_bfloat16 lo = __float2bfloat16(v - __bfloat162float(hi));
        const size_t o = (size_t)(nx + ty + j) * K + ky + tx;
        Th[o] = hi; Tl[o] = lo;
    }
}

// ---------------------------------------------------------------------------
// RoPE cos/sin tables
// ---------------------------------------------------------------------------
__global__ void rope_tab(float* __restrict__ c, float* __restrict__ s)
{
    const int i = blockIdx.x * blockDim.x + threadIdx.x;
    const int t = i >> 6, p = i & 63;
    const float inv_freq = powf(10000.0f, -(float)p * (1.0f / 64.0f));
    float sn, cs;
    sincosf((float)t * inv_freq, &sn, &cs);
    c[i] = cs; s[i] = sn;
}

// ---------------------------------------------------------------------------
// prep_qkv: RoPE + scale + split hi/lo head-major; v transpose+split.
// ---------------------------------------------------------------------------
#define PREP_SMEM (128 * 133 * 4)

__global__ __launch_bounds__(256, 1) void prep_qkv(
    const float* __restrict__ qkv,
    const float* __restrict__ rc, const float* __restrict__ rs,
    __nv_bfloat16* __restrict__ Qh, __nv_bfloat16* __restrict__ Ql,
    __nv_bfloat16* __restrict__ Kh, __nv_bfloat16* __restrict__ Kl,
    __nv_bfloat16* __restrict__ Vh, __nv_bfloat16* __restrict__ Vl)
{
    extern __shared__ float ps[];
    const int tid = threadIdx.x;
    const int bh = blockIdx.y;
    const int b = bh >> 5, h = bh & 31;
    const int s0 = blockIdx.x * 128;
    const float scale = 0.08838834764831843f;

    #pragma unroll 4
    for (int i = 0; i < 32; i++) {
        const int idx = tid + i * 256;
        const int sr = idx >> 6, p = idx & 63;
        const int sg = s0 + sr;
        const size_t base = ((size_t)b * S_ + sg) * QKV_N + h * HD;
        const float cs = rc[sg * 64 + p], sn = rs[sg * 64 + p];
        const float q1 = qkv[base + p],        q2 = qkv[base + p + 64];
        const float k1 = qkv[base + H_ + p],   k2 = qkv[base + H_ + p + 64];
        const float qa = (q1 * cs - q2 * sn) * scale;
        const float qb = (q2 * cs + q1 * sn) * scale;
        const float ka = k1 * cs - k2 * sn;
        const float kb = k2 * cs + k1 * sn;
        const size_t ob = ((size_t)bh * S_ + sg) * HD;
        __nv_bfloat16 t;
        t = __float2bfloat16(qa); Qh[ob + p] = t;      Ql[ob + p]      = __float2bfloat16(qa - __bfloat162float(t));
        t = __float2bfloat16(qb); Qh[ob + p + 64] = t; Ql[ob + p + 64] = __float2bfloat16(qb - __bfloat162float(t));
        t = __float2bfloat16(ka); Kh[ob + p] = t;      Kl[ob + p]      = __float2bfloat16(ka - __bfloat162float(t));
        t = __float2bfloat16(kb); Kh[ob + p + 64] = t; Kl[ob + p + 64] = __float2bfloat16(kb - __bfloat162float(t));
    }

    #pragma unroll 4
    for (int i = 0; i < 64; i++) {
        const int idx = tid + i * 256;
        const int sr = idx >> 7, p = idx & 127;
        ps[sr * 133 + p] = qkv[((size_t)b * S_ + s0 + sr) * QKV_N + h * HD + 2 * H_ + p];
    }
    __syncthreads();
    #pragma unroll 4
    for (int i = 0; i < 64; i++) {
        const int idx = tid + i * 256;
        const int d = idx >> 7, sr = idx & 127;
        const float v = ps[sr * 133 + d];
        const __nv_bfloat16 hi = __float2bfloat16(v);
        const size_t o = ((size_t)bh * HD + d) * S_ + s0 + sr;
        Vh[o] = hi;
        Vl[o] = __float2bfloat16(v - __bfloat162float(hi));
    }
}

// ---------------------------------------------------------------------------
// Flash attention, mma.sync bf16x3 (unchanged from R5)
// ---------------------------------------------------------------------------
#define FQ_LD 136
#define FV_LD 72
#define SQ_ELEMS (128 * FQ_LD)
#define SK_ELEMS (64 * FQ_LD)
#define SV_ELEMS (128 * FV_LD)
#define FSTAGE (2 * SK_ELEMS + 2 * SV_ELEMS)
#define FLASH_SMEM ((2 * SQ_ELEMS + 2 * FSTAGE) * 2)

__global__ __launch_bounds__(256, 1) void flash_mma(
    const __nv_bfloat16* __restrict__ Qh, const __nv_bfloat16* __restrict__ Ql,
    const __nv_bfloat16* __restrict__ Kh, const __nv_bfloat16* __restrict__ Kl,
    const __nv_bfloat16* __restrict__ Vh, const __nv_bfloat16* __restrict__ Vl,
    __nv_bfloat16* __restrict__ Ch, __nv_bfloat16* __restrict__ Cl)
{
    extern __shared__ __nv_bfloat16 fs[];
    const int tid = threadIdx.x;
    const int lane = tid & 31;
    const int w = tid >> 5;
    const int qblk = blockIdx.x;
    const int bh = blockIdx.y;
    const int b = bh >> 5, h = bh & 31;
    const int q0 = qblk * 128;
    const uint32_t sb = smem_u32(fs);

    const size_t hoff = (size_t)bh * S_ * HD;
    const size_t voff = (size_t)bh * HD * S_;

    #pragma unroll
    for (int i = 0; i < 8; i++) {
        const int idx = tid + i * 256;
        const int r = idx >> 4, seg = idx & 15;
        const size_t go = hoff + (size_t)(q0 + r) * HD + seg * 8;
        const uint32_t so = (r * FQ_LD + seg * 8) * 2;
        CP_ASYNC16(sb + so, Qh + go);
        CP_ASYNC16(sb + SQ_ELEMS * 2 + so, Ql + go);
    }

    auto load_kv = [&](int t, int s) {
        const int k0 = t * 64;
        const uint32_t st = sb + (2 * SQ_ELEMS + s * FSTAGE) * 2;
        #pragma unroll
        for (int i = 0; i < 4; i++) {
            const int idx = tid + i * 256;
            const int r = idx >> 4, seg = idx & 15;
            const size_t go = hoff + (size_t)(k0 + r) * HD + seg * 8;
            const uint32_t so = (r * FQ_LD + seg * 8) * 2;
            CP_ASYNC16(st + so, Kh + go);
            CP_ASYNC16(st + SK_ELEMS * 2 + so, Kl + go);
        }
        #pragma unroll
        for (int i = 0; i < 4; i++) {
            const int idx = tid + i * 256;
            const int r = idx >> 3, seg = idx & 7;
            const size_t go = voff + (size_t)r * S_ + k0 + seg * 8;
            const uint32_t so = (2 * SK_ELEMS + r * FV_LD + seg * 8) * 2;
            CP_ASYNC16(st + so, Vh + go);
            CP_ASYNC16(st + SV_ELEMS * 2 + so, Vl + go);
        }
        CP_COMMIT();
    };

    load_kv(0, 0);

    float O[16][4];
    #pragma unroll
    for (int i = 0; i < 16; i++)
        #pragma unroll
        for (int j = 0; j < 4; j++) O[i][j] = 0.f;
    float m0 = -1e30f, m1 = -1e30f, l0 = 0.f, l1 = 0.f;

    const int r0 = w * 16 + (lane >> 2);
    const int cq = (lane & 3) * 2;
    const int ntiles = 2 * qblk + 2;

    for (int t = 0; t < ntiles; t++) {
        if (t + 1 < ntiles) { load_kv(t + 1, (t + 1) & 1); CP_WAIT1(); }
        else                { CP_WAIT0(); }
        __syncthreads();

        const __nv_bfloat16* sQh = fs;
        const __nv_bfloat16* sQl = fs + SQ_ELEMS;
        const __nv_bfloat16* sKh = fs + 2 * SQ_ELEMS + (t & 1) * FSTAGE;
        const __nv_bfloat16* sKl = sKh + SK_ELEMS;
        const __nv_bfloat16* sVh = sKl + SK_ELEMS;
        const __nv_bfloat16* sVl = sVh + SV_ELEMS;

        float Sf[8][4];
        #pragma unroll
        for (int nt = 0; nt < 8; nt++)
            #pragma unroll
            for (int j = 0; j < 4; j++) Sf[nt][j] = 0.f;

        #pragma unroll
        for (int kk = 0; kk < 8; kk++) {
            uint32_t ah[4], al[4];
            const __nv_bfloat16* qp = sQh + r0 * FQ_LD + kk * 16 + cq;
            const __nv_bfloat16* qp2 = sQl + r0 * FQ_LD + kk * 16 + cq;
            ah[0] = *(const uint32_t*)(qp);
            ah[1] = *(const uint32_t*)(qp + 8 * FQ_LD);
            ah[2] = *(const uint32_t*)(qp + 8);
            ah[3] = *(const uint32_t*)(qp + 8 * FQ_LD + 8);
            al[0] = *(const uint32_t*)(qp2);
            al[1] = *(const uint32_t*)(qp2 + 8 * FQ_LD);
            al[2] = *(const uint32_t*)(qp2 + 8);
            al[3] = *(const uint32_t*)(qp2 + 8 * FQ_LD + 8);
            uint32_t khf[8][2];
            #pragma unroll
            for (int nt = 0; nt < 8; nt++) {
                const int n = nt * 8 + (lane >> 2);
                const __nv_bfloat16* kp = sKh + n * FQ_LD + kk * 16 + cq;
                khf[nt][0] = *(const uint32_t*)(kp);
                khf[nt][1] = *(const uint32_t*)(kp + 8);
            }
            #pragma unroll
            for (int nt = 0; nt < 8; nt++)
                mma_bf16(Sf[nt], ah, khf[nt][0], khf[nt][1]);
            #pragma unroll
            for (int nt = 0; nt < 8; nt++)
                mma_bf16(Sf[nt], al, khf[nt][0], khf[nt][1]);
            #pragma unroll
            for (int nt = 0; nt < 8; nt++) {
                const int n = nt * 8 + (lane >> 2);
                const __nv_bfloat16* kp2 = sKl + n * FQ_LD + kk * 16 + cq;
                mma_bf16(Sf[nt], ah, *(const uint32_t*)(kp2),
                                     *(const uint32_t*)(kp2 + 8));
            }
        }

        const int k0 = t * 64;
        const int qg0 = q0 + r0, qg1 = qg0 + 8;
        if (k0 + 63 > q0 + w * 16) {
            #pragma unroll
            for (int nt = 0; nt < 8; nt++) {
                const int kv = k0 + nt * 8 + cq;
                if (kv     > qg0) Sf[nt][0] = -1e30f;
                if (kv + 1 > qg0) Sf[nt][1] = -1e30f;
                if (kv     > qg1) Sf[nt][2] = -1e30f;
                if (kv + 1 > qg1) Sf[nt][3] = -1e30f;
            }
        }
        float mx0 = -1e30f, mx1 = -1e30f;
        #pragma unroll
        for (int nt = 0; nt < 8; nt++) {
            mx0 = fmaxf(mx0, fmaxf(Sf[nt][0], Sf[nt][1]));
            mx1 = fmaxf(mx1, fmaxf(Sf[nt][2], Sf[nt][3]));
        }
        mx0 = fmaxf(mx0, __shfl_xor_sync(0xffffffffu, mx0, 1));
        mx0 = fmaxf(mx0, __shfl_xor_sync(0xffffffffu, mx0, 2));
        mx1 = fmaxf(mx1, __shfl_xor_sync(0xffffffffu, mx1, 1));
        mx1 = fmaxf(mx1, __shfl_xor_sync(0xffffffffu, mx1, 2));

        const float mn0 = fmaxf(m0, mx0), mn1 = fmaxf(m1, mx1);
        const float a0 = __expf(m0 - mn0), a1 = __expf(m1 - mn1);
        m0 = mn0; m1 = mn1;

        float s0 = 0.f, s1 = 0.f;
        uint32_t Ph[8][2], Pl[8][2];
        #pragma unroll
        for (int nt = 0; nt < 8; nt++) {
            const float p00 = __expf(Sf[nt][0] - mn0);
            const float p01 = __expf(Sf[nt][1] - mn0);
            const float p10 = __expf(Sf[nt][2] - mn1);
            const float p11 = __expf(Sf[nt][3] - mn1);
            s0 += p00 + p01; s1 += p10 + p11;
            const __nv_bfloat16 h00 = __float2bfloat16(p00);
            const __nv_bfloat16 h01 = __float2bfloat16(p01);
            const __nv_bfloat16 h10 = __float2bfloat16(p10);
            const __nv_bfloat16 h11 = __float2bfloat16(p11);
            Ph[nt][0] = (uint32_t)__bfloat16_as_ushort(h00) | ((uint32_t)__bfloat16_as_ushort(h01) << 16);
            Ph[nt][1] = (uint32_t)__bfloat16_as_ushort(h10) | ((uint32_t)__bfloat16_as_ushort(h11) << 16);
            Pl[nt][0] = packbf(p00 - __bfloat162float(h00), p01 - __bfloat162float(h01));
            Pl[nt][1] = packbf(p10 - __bfloat162float(h10), p11 - __bfloat162float(h11));
        }
        s0 += __shfl_xor_sync(0xffffffffu, s0, 1);
        s0 += __shfl_xor_sync(0xffffffffu, s0, 2);
        s1 += __shfl_xor_sync(0xffffffffu, s1, 1);
        s1 += __shfl_xor_sync(0xffffffffu, s1, 2);
        l0 = l0 * a0 + s0;
        l1 = l1 * a1 + s1;

        #pragma unroll
        for (int i = 0; i < 16; i++) {
            O[i][0] *= a0; O[i][1] *= a0; O[i][2] *= a1; O[i][3] *= a1;
        }

        #pragma unroll
        for (int ks = 0; ks < 4; ks++) {
            const uint32_t ah[4] = {Ph[2 * ks][0], Ph[2 * ks][1],
                                    Ph[2 * ks + 1][0], Ph[2 * ks + 1][1]};
            const uint32_t al[4] = {Pl[2 * ks][0], Pl[2 * ks][1],
                                    Pl[2 * ks + 1][0], Pl[2 * ks + 1][1]};
            #pragma unroll
            for (int nt2 = 0; nt2 < 16; nt2++) {
                const int nd = nt2 * 8 + (lane >> 2);
                const __nv_bfloat16* vp = sVh + nd * FV_LD + ks * 16 + cq;
                mma_bf16(O[nt2], ah, *(const uint32_t*)(vp),
                                     *(const uint32_t*)(vp + 8));
            }
            #pragma unroll
            for (int nt2 = 0; nt2 < 16; nt2++) {
                const int nd = nt2 * 8 + (lane >> 2);
                const __nv_bfloat16* vp2 = sVl + nd * FV_LD + ks * 16 + cq;
                mma_bf16(O[nt2], ah, *(const uint32_t*)(vp2),
                                     *(const uint32_t*)(vp2 + 8));
            }
            #pragma unroll
            for (int nt2 = 0; nt2 < 16; nt2++) {
                const int nd = nt2 * 8 + (lane >> 2);
                const __nv_bfloat16* vp = sVh + nd * FV_LD + ks * 16 + cq;
                mma_bf16(O[nt2], al, *(const uint32_t*)(vp),
                                     *(const uint32_t*)(vp + 8));
            }
        }
        __syncthreads();
    }

    const float inv0 = 1.f / l0, inv1 = 1.f / l1;
    const int row0 = q0 + w * 16 + (lane >> 2);
    const size_t o0 = ((size_t)b * S_ + row0) * H_ + h * HD + cq;
    const size_t o1 = o0 + 8 * (size_t)H_;
    #pragma unroll
    for (int nt2 = 0; nt2 < 16; nt2++) {
        const float f0 = O[nt2][0] * inv0, f1 = O[nt2][1] * inv0;
        const float f2 = O[nt2][2] * inv1, f3 = O[nt2][3] * inv1;
        const __nv_bfloat16 h0 = __float2bfloat16(f0), h1 = __float2bfloat16(f1);
        const __nv_bfloat16 h2 = __float2bfloat16(f2), h3 = __float2bfloat16(f3);
        *(uint32_t*)&Ch[o0 + nt2 * 8] =
            (uint32_t)__bfloat16_as_ushort(h0) | ((uint32_t)__bfloat16_as_ushort(h1) << 16);
        *(uint32_t*)&Ch[o1 + nt2 * 8] =
            (uint32_t)__bfloat16_as_ushort(h2) | ((uint32_t)__bfloat16_as_ushort(h3) << 16);
        *(uint32_t*)&Cl[o0 + nt2 * 8] =
            packbf(f0 - __bfloat162float(h0), f1 - __bfloat162float(h1));
        *(uint32_t*)&Cl[o1 + nt2 * 8] =
            packbf(f2 - __bfloat162float(h2), f3 - __bfloat162float(h3));
    }
}

// ---------------------------------------------------------------------------
// Launch
// ---------------------------------------------------------------------------
extern "C" void kernel_launch(void* const* d_in, const int* in_sizes, int n_in,
                              void* d_out, int out_size)
{
    const float* x    = (const float*)d_in[0];
    const float* Wqkv = (const float*)d_in[1];
    const float* Wo   = (const float*)d_in[2];
    float* out = (float*)d_out;

    float *qkv, *rc, *rs;
    __nv_bfloat16 *xh, *xl, *wqh, *wql, *woh, *wol, *ch, *cl;
    __nv_bfloat16 *qh, *ql, *kh, *kl, *vth, *vtl;
    cudaGetSymbolAddress((void**)&qkv, g_qkv);
    cudaGetSymbolAddress((void**)&rc, g_rcos);
    cudaGetSymbolAddress((void**)&rs, g_rsin);
    cudaGetSymbolAddress((void**)&xh, g_xh);
    cudaGetSymbolAddress((void**)&xl, g_xl);
    cudaGetSymbolAddress((void**)&wqh, g_wqh);
    cudaGetSymbolAddress((void**)&wql, g_wql);
    cudaGetSymbolAddress((void**)&woh, g_woh);
    cudaGetSymbolAddress((void**)&wol, g_wol);
    cudaGetSymbolAddress((void**)&ch, g_ch);
    cudaGetSymbolAddress((void**)&cl, g_cl);
    cudaGetSymbolAddress((void**)&qh, g_qh);
    cudaGetSymbolAddress((void**)&ql, g_ql);
    cudaGetSymbolAddress((void**)&kh, g_kh);
    cudaGetSymbolAddress((void**)&kl, g_kl);
    cudaGetSymbolAddress((void**)&vth, g_vth);
    cudaGetSymbolAddress((void**)&vtl, g_vtl);

    cudaFuncSetAttribute(gemm_bf16x3mma,
                         cudaFuncAttributeMaxDynamicSharedMemorySize, GEMM_SMEM);
    cudaFuncSetAttribute(prep_qkv,
                         cudaFuncAttributeMaxDynamicSharedMemorySize, PREP_SMEM);
    cudaFuncSetAttribute(flash_mma,
                         cudaFuncAttributeMaxDynamicSharedMemorySize, FLASH_SMEM);

    {
        const int n4 = (BS_ * H_) / 4;
        split_kernel<<<n4 / 256, 256>>>((const float4*)x, (uint2*)xh, (uint2*)xl, n4);
    }
    {
        dim3 grid(QKV_N / 32, H_ / 32), blk(32, 8);
        transpose_split<<<grid, blk>>>(Wqkv, wqh, wql, H_, QKV_N);
    }
    {
        dim3 grid(H_ / 32, H_ / 32), blk(32, 8);
        transpose_split<<<grid, blk>>>(Wo, woh, wol, H_, H_);
    }
    rope_tab<<<(S_ * 64) / 256, 256>>>(rc, rs);

    {
        dim3 grid(BS_ / 128, QKV_N / 256);
        gemm_bf16x3mma<<<grid, 256, GEMM_SMEM>>>(xh, xl, wqh, wql, qkv, QKV_N, H_);
    }
    {
        dim3 grid(S_ / 128, B_ * NH);
        prep_qkv<<<grid, 256, PREP_SMEM>>>(qkv, rc, rs, qh, ql, kh, kl, vth, vtl);
    }
    {
        dim3 grid(S_ / 128, B_ * NH);
        flash_mma<<<grid, 256, FLASH_SMEM>>>(qh, ql, kh, kl, vth, vtl, ch, cl);
    }
    {
        dim3 grid(BS_ / 128, H_ / 256);
        gemm_bf16x3mma<<<grid, 256, GEMM_SMEM>>>(ch, cl, woh, wol, out, H_, H_);
    }
}